// round 1
// baseline (speedup 1.0000x reference)
#include <cuda_runtime.h>

// Problem constants
constexpr int kB = 4;
constexpr int kN = 1024;
constexpr int kD = 256;
constexpr int kH = 8;
constexpr int kDH  = kD * kH;          // 2048
constexpr int kNDH = kN * kDH;         // 2097152 (2^21)
constexpr int kSeg = kB * kNDH;        // 8388608 (2^23) — q/k/v segment size
constexpr int kC3  = 3 * kDH;          // 6144
constexpr int kRows = kB * kN;         // 4096

// Scratch (device globals; no dynamic allocation allowed)
__device__ float g_qkv[3ull * kB * kN * kD * kH];   // 25165824 floats (~100.7 MB)
__device__ float g_diag[kB * kN * kH];              // 32768 floats

// ---------------------------------------------------------------------------
// Kernel 1: QKV = x @ Wqkv + bqkv      [4096,256] @ [256,6144] -> g_qkv
// 128x128 CTA tile, 256 threads, 8x8 per-thread microtile, K chunks of 32.
// ---------------------------------------------------------------------------
__global__ __launch_bounds__(256, 2)
void qkv_gemm_kernel(const float* __restrict__ x,
                     const float* __restrict__ W,
                     const float* __restrict__ bias)
{
    __shared__ float As[128][33];
    __shared__ float Bs[32][128];

    const int t  = threadIdx.x;
    const int tx = t & 15, ty = t >> 4;
    const int r0 = blockIdx.y * 128;
    const int c0 = blockIdx.x * 128;

    float acc[8][8];
#pragma unroll
    for (int i = 0; i < 8; i++)
#pragma unroll
        for (int j = 0; j < 8; j++) acc[i][j] = 0.f;

    const int kkA = t & 31, mbA = t >> 5;     // A loader: lane over k, 16 rows/thread
    const int cB  = t & 127, kbB = t >> 7;    // B loader: lane over c, 16 rows/thread

    for (int kc = 0; kc < kD; kc += 32) {
#pragma unroll
        for (int i = 0; i < 16; i++) {
            int m = mbA + i * 8;
            As[m][kkA] = x[(r0 + m) * kD + kc + kkA];
        }
#pragma unroll
        for (int i = 0; i < 16; i++) {
            int k2 = kbB + i * 2;
            Bs[k2][cB] = W[(size_t)(kc + k2) * kC3 + c0 + cB];
        }
        __syncthreads();
#pragma unroll
        for (int kq = 0; kq < 32; kq++) {
            float a[8], b[8];
#pragma unroll
            for (int i = 0; i < 8; i++) a[i] = As[ty * 8 + i][kq];
            float4 bv0 = *(const float4*)&Bs[kq][tx * 8];
            float4 bv1 = *(const float4*)&Bs[kq][tx * 8 + 4];
            b[0] = bv0.x; b[1] = bv0.y; b[2] = bv0.z; b[3] = bv0.w;
            b[4] = bv1.x; b[5] = bv1.y; b[6] = bv1.z; b[7] = bv1.w;
#pragma unroll
            for (int i = 0; i < 8; i++)
#pragma unroll
                for (int j = 0; j < 8; j++)
                    acc[i][j] = fmaf(a[i], b[j], acc[i][j]);
        }
        __syncthreads();
    }

#pragma unroll
    for (int i = 0; i < 8; i++) {
        int r = r0 + ty * 8 + i;
#pragma unroll
        for (int j = 0; j < 8; j += 4) {
            int c = c0 + tx * 8 + j;
            float4 v;
            v.x = acc[i][j + 0] + bias[c + 0];
            v.y = acc[i][j + 1] + bias[c + 1];
            v.z = acc[i][j + 2] + bias[c + 2];
            v.w = acc[i][j + 3] + bias[c + 3];
            *(float4*)&g_qkv[(size_t)r * kC3 + c] = v;
        }
    }
}

// ---------------------------------------------------------------------------
// Kernel 2: per (b,h), S[m,n] = (1/16) * sum_qd q[b,m,qd,h]*k[b,n,qd,h],
// softmax over m per column n (online), keep only the diagonal:
//   g_diag[b,n,h] = exp(S[n,n]-colmax) / colsumexp
// CTA: 64 columns of one (b,h). 256 threads, 8x4 microtile over 128m x 64n.
// Dynamic smem: Ks[256][65] + Qs[128][33] + red[16][64] + 4*[64]
// ---------------------------------------------------------------------------
__global__ __launch_bounds__(256, 1)
void score_diag_kernel()
{
    extern __shared__ float sm[];
    float* Ks     = sm;                  // [256][65]
    float* Qs     = Ks + 256 * 65;       // [128][33]
    float* red    = Qs + 128 * 33;       // [16][64]
    float* runmax = red + 16 * 64;       // [64]
    float* runsum = runmax + 64;         // [64]
    float* nmv    = runsum + 64;         // [64]
    float* diagS  = nmv + 64;            // [64]

    const int t  = threadIdx.x;
    const int tx = t & 15, ty = t >> 4;
    const int bh = blockIdx.y;
    const int b  = bh >> 3, h = bh & 7;
    const int n0 = blockIdx.x * 64;

    const float* qbase = g_qkv + (size_t)b * kNDH;
    const float* kbase = g_qkv + (size_t)kSeg + (size_t)b * kNDH;

    // Load K column tile once: Ks[qd][n] for n in [n0, n0+64)
    {
        const int qd = t;  // 0..255
        const float* kp = kbase + (size_t)n0 * kDH + qd * kH + h;
#pragma unroll 8
        for (int i = 0; i < 64; i++)
            Ks[qd * 65 + i] = kp[(size_t)i * kDH];
    }
    if (t < 64) { runmax[t] = -1e30f; runsum[t] = 0.f; }
    __syncthreads();

    const int kkQ = t & 31, mbQ = t >> 5;

    for (int mt = 0; mt < 8; mt++) {
        const int m0 = mt * 128;
        float acc[8][4];
#pragma unroll
        for (int i = 0; i < 8; i++)
#pragma unroll
            for (int j = 0; j < 4; j++) acc[i][j] = 0.f;

        for (int qc = 0; qc < kD; qc += 32) {
#pragma unroll
            for (int i = 0; i < 16; i++) {
                int m = mbQ + i * 8;
                Qs[m * 33 + kkQ] =
                    qbase[(size_t)(m0 + m) * kDH + (qc + kkQ) * kH + h];
            }
            __syncthreads();
#pragma unroll
            for (int kq = 0; kq < 32; kq++) {
                float a[8];
#pragma unroll
                for (int i = 0; i < 8; i++) a[i] = Qs[(ty * 8 + i) * 33 + kq];
                float bb[4];
#pragma unroll
                for (int j = 0; j < 4; j++) bb[j] = Ks[(qc + kq) * 65 + tx * 4 + j];
#pragma unroll
                for (int i = 0; i < 8; i++)
#pragma unroll
                    for (int j = 0; j < 4; j++)
                        acc[i][j] = fmaf(a[i], bb[j], acc[i][j]);
            }
            __syncthreads();
        }

        // scale by d^-0.5 = 1/16
#pragma unroll
        for (int i = 0; i < 8; i++)
#pragma unroll
            for (int j = 0; j < 4; j++) acc[i][j] *= 0.0625f;

        // tile column max (over 128 m-rows)
#pragma unroll
        for (int j = 0; j < 4; j++) {
            float tm = acc[0][j];
#pragma unroll
            for (int i = 1; i < 8; i++) tm = fmaxf(tm, acc[i][j]);
            red[ty * 64 + tx * 4 + j] = tm;
        }
        __syncthreads();
        if (t < 64) {
            float m_ = red[t];
#pragma unroll
            for (int r = 1; r < 16; r++) m_ = fmaxf(m_, red[r * 64 + t]);
            float nn = fmaxf(runmax[t], m_);
            runsum[t] *= __expf(runmax[t] - nn);  // rescale old sum
            runmax[t] = nn;
            nmv[t] = nn;
        }
        __syncthreads();

        // tile column sum of exp(S - newmax)
#pragma unroll
        for (int j = 0; j < 4; j++) {
            float nn = nmv[tx * 4 + j];
            float s = 0.f;
#pragma unroll
            for (int i = 0; i < 8; i++) s += __expf(acc[i][j] - nn);
            red[ty * 64 + tx * 4 + j] = s;
        }
        // capture diagonal raw score (exactly one thread per column ever hits)
#pragma unroll
        for (int i = 0; i < 8; i++) {
            int gm = m0 + ty * 8 + i;
#pragma unroll
            for (int j = 0; j < 4; j++) {
                int gn = n0 + tx * 4 + j;
                if (gm == gn) diagS[tx * 4 + j] = acc[i][j];
            }
        }
        __syncthreads();
        if (t < 64) {
            float s = 0.f;
#pragma unroll
            for (int r = 0; r < 16; r++) s += red[r * 64 + t];
            runsum[t] += s;
        }
        __syncthreads();
    }

    if (t < 64) {
        float da = __expf(diagS[t] - runmax[t]) / runsum[t];
        g_diag[((size_t)b * kN + (n0 + t)) * kH + h] = da;
    }
}

// ---------------------------------------------------------------------------
// Kernel 3: out = (diag .* v) @ W0 + b0    [4096,2048] @ [2048,256]
// Av[r,c] = g_diag[r*8 + (c&7)] * vseg[r*2048 + c]
// 64x64 CTA tile, 256 threads, 4x4 microtile, K chunks of 32.
// ---------------------------------------------------------------------------
__global__ __launch_bounds__(256, 4)
void out_gemm_kernel(const float* __restrict__ W0,
                     const float* __restrict__ b0,
                     float* __restrict__ out)
{
    __shared__ float As[64][33];
    __shared__ float Ws[32][64];
    __shared__ float dsm[64][8];

    const int t  = threadIdx.x;
    const int tx = t & 15, ty = t >> 4;
    const int c0 = blockIdx.x * 64;
    const int r0 = blockIdx.y * 64;
    const float* vseg = g_qkv + 2ull * kSeg;

    for (int idx = t; idx < 512; idx += 256)
        dsm[idx >> 3][idx & 7] = g_diag[(size_t)(r0 + (idx >> 3)) * kH + (idx & 7)];
    __syncthreads();

    float acc[4][4];
#pragma unroll
    for (int i = 0; i < 4; i++)
#pragma unroll
        for (int j = 0; j < 4; j++) acc[i][j] = 0.f;

    const int kkA = t & 31, mbA = t >> 5;
    const int cW  = t & 63, kbW = t >> 6;

    for (int k0 = 0; k0 < kDH; k0 += 32) {
#pragma unroll
        for (int i = 0; i < 8; i++) {
            int m = mbA + i * 8;
            As[m][kkA] = dsm[m][kkA & 7] *
                         vseg[(size_t)(r0 + m) * kDH + k0 + kkA];
        }
#pragma unroll
        for (int i = 0; i < 8; i++) {
            int k2 = kbW + i * 4;
            Ws[k2][cW] = W0[(size_t)(k0 + k2) * kD + c0 + cW];
        }
        __syncthreads();
#pragma unroll
        for (int kq = 0; kq < 32; kq++) {
            float a[4];
#pragma unroll
            for (int i = 0; i < 4; i++) a[i] = As[ty * 4 + i][kq];
            float4 bv = *(const float4*)&Ws[kq][tx * 4];
            float b[4] = {bv.x, bv.y, bv.z, bv.w};
#pragma unroll
            for (int i = 0; i < 4; i++)
#pragma unroll
                for (int j = 0; j < 4; j++)
                    acc[i][j] = fmaf(a[i], b[j], acc[i][j]);
        }
        __syncthreads();
    }

#pragma unroll
    for (int i = 0; i < 4; i++) {
        int r = r0 + ty * 4 + i;
        int c = c0 + tx * 4;
        float4 v;
        v.x = acc[i][0] + b0[c + 0];
        v.y = acc[i][1] + b0[c + 1];
        v.z = acc[i][2] + b0[c + 2];
        v.w = acc[i][3] + b0[c + 3];
        *(float4*)&out[(size_t)r * kD + c] = v;
    }
}

// ---------------------------------------------------------------------------
extern "C" void kernel_launch(void* const* d_in, const int* in_sizes, int n_in,
                              void* d_out, int out_size)
{
    // Robust input identification by element count (all distinct).
    const float *x = nullptr, *Wqkv = nullptr, *bqkv = nullptr,
                *W0 = nullptr, *b0 = nullptr;
    for (int i = 0; i < n_in; i++) {
        switch (in_sizes[i]) {
            case kRows * kD:      x    = (const float*)d_in[i]; break; // 1048576
            case kD * kC3:        Wqkv = (const float*)d_in[i]; break; // 1572864
            case kC3:             bqkv = (const float*)d_in[i]; break; // 6144
            case kDH * kD:        W0   = (const float*)d_in[i]; break; // 524288
            case kD:              b0   = (const float*)d_in[i]; break; // 256
            default: break;
        }
    }
    float* out = (float*)d_out;

    const size_t smem2 = (size_t)(256 * 65 + 128 * 33 + 16 * 64 + 4 * 64) * sizeof(float);
    cudaFuncSetAttribute(score_diag_kernel,
                         cudaFuncAttributeMaxDynamicSharedMemorySize, (int)smem2);

    qkv_gemm_kernel<<<dim3(kC3 / 128, kRows / 128), 256>>>(x, Wqkv, bqkv);
    score_diag_kernel<<<dim3(kN / 64, kB * kH), 256, smem2>>>();
    out_gemm_kernel<<<dim3(kD / 64, kRows / 64), 256>>>(W0, b0, out);
}

// round 2
// speedup vs baseline: 1.1888x; 1.1888x over previous
#include <cuda_runtime.h>

// Problem constants
constexpr int kB = 4;
constexpr int kN = 1024;
constexpr int kD = 256;
constexpr int kH = 8;
constexpr int kDH  = kD * kH;          // 2048
constexpr int kNDH = kN * kDH;         // 2097152
constexpr int kSeg = kB * kNDH;        // 8388608  (q/k/v segment, floats)
constexpr int kC3  = 3 * kDH;          // 6144
constexpr int kRows = kB * kN;         // 4096

// Scratch (device globals; no dynamic allocation allowed)
__device__ float g_qkv[3ull * kSeg];   // ~100.7 MB : QKV in reference flat layout
__device__ float g_qkT[2ull * kSeg];   // ~64 MB    : q,k transposed to [seg][b][h][n][qd]
__device__ float g_diag[kRows * kH];

// ---------------- cp.async helpers ----------------
__device__ __forceinline__ void cp16(void* smem_dst, const void* gmem_src) {
    unsigned s = (unsigned)__cvta_generic_to_shared(smem_dst);
    asm volatile("cp.async.cg.shared.global [%0], [%1], 16;\n" :: "r"(s), "l"(gmem_src));
}
__device__ __forceinline__ void cp_commit() {
    asm volatile("cp.async.commit_group;\n");
}
template <int N>
__device__ __forceinline__ void cp_wait() {
    asm volatile("cp.async.wait_group %0;\n" :: "n"(N));
}

// ---------------------------------------------------------------------------
// Kernel 1: QKV = x @ Wqkv + bqkv     [4096,256] @ [256,6144]
// 128x128 CTA tile, 256 threads, 8x8 microtile (2x2 groups of 4x4),
// A kept m-major in smem, k unrolled by 4 (all LDS.128), cp.async dbl-buffer.
// ---------------------------------------------------------------------------
__global__ __launch_bounds__(256, 2)
void qkv_gemm_kernel(const float* __restrict__ x,
                     const float* __restrict__ W,
                     const float* __restrict__ bias)
{
    extern __shared__ float sm[];
    float* As = sm;                    // [2][128][36]
    float* Bs = sm + 2 * 128 * 36;     // [2][32][132]

    const int t  = threadIdx.x;
    const int tx = t & 15, ty = t >> 4;
    const int r0 = blockIdx.y * 128;
    const int c0 = blockIdx.x * 128;

    const int af = t & 7,  am = t >> 3;   // A loader: float4 col af, rows am+32i
    const int bc = t & 31, bk = t >> 5;   // B loader: float4 col bc, rows bk+8i

    float acc[8][8];
#pragma unroll
    for (int i = 0; i < 8; i++)
#pragma unroll
        for (int j = 0; j < 8; j++) acc[i][j] = 0.f;

    // preload chunk 0
#pragma unroll
    for (int i = 0; i < 4; i++) {
        int m = am + i * 32;
        cp16(&As[m * 36 + af * 4], &x[(size_t)(r0 + m) * kD + af * 4]);
    }
#pragma unroll
    for (int i = 0; i < 4; i++) {
        int k = bk + i * 8;
        cp16(&Bs[k * 132 + bc * 4], &W[(size_t)k * kC3 + c0 + bc * 4]);
    }
    cp_commit();

    for (int c = 0; c < 8; c++) {
        const int buf = c & 1;
        if (c < 7) {
            const int kc = (c + 1) * 32;
            const int nb = buf ^ 1;
#pragma unroll
            for (int i = 0; i < 4; i++) {
                int m = am + i * 32;
                cp16(&As[nb * 128 * 36 + m * 36 + af * 4],
                     &x[(size_t)(r0 + m) * kD + kc + af * 4]);
            }
#pragma unroll
            for (int i = 0; i < 4; i++) {
                int k = bk + i * 8;
                cp16(&Bs[nb * 32 * 132 + k * 132 + bc * 4],
                     &W[(size_t)(kc + k) * kC3 + c0 + bc * 4]);
            }
            cp_commit();
            cp_wait<1>();
        } else {
            cp_wait<0>();
        }
        __syncthreads();

        const float* A_ = &As[buf * 128 * 36];
        const float* B_ = &Bs[buf * 32 * 132];
#pragma unroll
        for (int kg = 0; kg < 32; kg += 4) {
            float4 av[8];
#pragma unroll
            for (int gi = 0; gi < 2; gi++)
#pragma unroll
                for (int i = 0; i < 4; i++)
                    av[gi * 4 + i] =
                        *(const float4*)&A_[(gi * 64 + ty * 4 + i) * 36 + kg];
#pragma unroll
            for (int kk = 0; kk < 4; kk++) {
                float4 b0 = *(const float4*)&B_[(kg + kk) * 132 + tx * 4];
                float4 b1 = *(const float4*)&B_[(kg + kk) * 132 + tx * 4 + 64];
#pragma unroll
                for (int r = 0; r < 8; r++) {
                    float a = (kk == 0) ? av[r].x : (kk == 1) ? av[r].y
                             : (kk == 2) ? av[r].z : av[r].w;
                    acc[r][0] = fmaf(a, b0.x, acc[r][0]);
                    acc[r][1] = fmaf(a, b0.y, acc[r][1]);
                    acc[r][2] = fmaf(a, b0.z, acc[r][2]);
                    acc[r][3] = fmaf(a, b0.w, acc[r][3]);
                    acc[r][4] = fmaf(a, b1.x, acc[r][4]);
                    acc[r][5] = fmaf(a, b1.y, acc[r][5]);
                    acc[r][6] = fmaf(a, b1.z, acc[r][6]);
                    acc[r][7] = fmaf(a, b1.w, acc[r][7]);
                }
            }
        }
        __syncthreads();
    }

#pragma unroll
    for (int gi = 0; gi < 2; gi++)
#pragma unroll
        for (int i = 0; i < 4; i++) {
            int r  = r0 + gi * 64 + ty * 4 + i;
            int rr = gi * 4 + i;
#pragma unroll
            for (int gj = 0; gj < 2; gj++) {
                int c = c0 + gj * 64 + tx * 4;
                float4 v;
                v.x = acc[rr][gj * 4 + 0] + bias[c + 0];
                v.y = acc[rr][gj * 4 + 1] + bias[c + 1];
                v.z = acc[rr][gj * 4 + 2] + bias[c + 2];
                v.w = acc[rr][gj * 4 + 3] + bias[c + 3];
                *(float4*)&g_qkv[(size_t)r * kC3 + c] = v;
            }
        }
}

// ---------------------------------------------------------------------------
// Transpose kernel: q,k segments of g_qkv -> g_qkT[seg][b][h][n][qd]
// so kernel 2 gets fully coalesced, non-overfetching loads.
// Tile: 32 n x 32 qd x 8 h per CTA. 2048 CTAs, 256 threads.
// ---------------------------------------------------------------------------
__global__ __launch_bounds__(256)
void transpose_qk_kernel()
{
    __shared__ float smt[8][32][33];   // [h][qd][n]
    const int bid = blockIdx.x;
    const int qb  = bid & 7;
    const int nb  = (bid >> 3) & 31;
    const int b   = (bid >> 8) & 3;
    const int seg = bid >> 10;
    const int t   = threadIdx.x;

    const float* src = g_qkv + (size_t)seg * kSeg + (size_t)b * kNDH
                     + (size_t)(nb * 32) * kDH + qb * 32 * 8;
    {
        const int nl = t >> 3, f = t & 7;
        const int h0 = (f & 1) * 4, q0 = f >> 1;
#pragma unroll
        for (int i = 0; i < 8; i++) {
            float4 v = *(const float4*)&src[(size_t)nl * kDH + (f + i * 8) * 4];
            int ql = q0 + i * 4;
            smt[h0 + 0][ql][nl] = v.x;
            smt[h0 + 1][ql][nl] = v.y;
            smt[h0 + 2][ql][nl] = v.z;
            smt[h0 + 3][ql][nl] = v.w;
        }
    }
    __syncthreads();
    {
        const int q4 = (t & 7) * 4, hn = t >> 3;
#pragma unroll
        for (int i = 0; i < 8; i++) {
            int idx = hn + i * 32;
            int h = idx >> 5, n = idx & 31;
            float4 v;
            v.x = smt[h][q4 + 0][n];
            v.y = smt[h][q4 + 1][n];
            v.z = smt[h][q4 + 2][n];
            v.w = smt[h][q4 + 3][n];
            float* dst = g_qkT + (size_t)seg * kSeg
                       + (((size_t)(b * 8 + h) * kN + nb * 32 + n) * kD)
                       + qb * 32 + q4;
            *(float4*)dst = v;
        }
    }
}

// ---------------------------------------------------------------------------
// Kernel 2: per (b,h): S[m,n] = (1/16) Q'[m,:]·K'[n,:]; column softmax over m;
// keep diagonal attn value. NT GEMM with float4-k-unroll, cp.async dbl-buffer.
// CTA: 64 n-cols, full m=1024 as 4 m-tiles of 256. 256 threads.
// Thread microtile: rows g*64+ty*4+i (g<4,i<4), cols tx+16j (j<4).
// ---------------------------------------------------------------------------
__global__ __launch_bounds__(256, 2)
void score_diag_kernel()
{
    extern __shared__ float sm[];
    float* As     = sm;                        // [2][256][36]
    float* Ks     = sm + 2 * 256 * 36;         // [2][64][36]
    float* red    = sm + 2 * 256 * 36 + 2 * 64 * 36;  // [16][64]
    float* runmax = red + 1024;                // [64]
    float* runsum = runmax + 64;               // [64]
    float* nmv    = runsum + 64;               // [64]
    float* diagS  = nmv + 64;                  // [64]

    const int t  = threadIdx.x;
    const int tx = t & 15, ty = t >> 4;
    const int bh = blockIdx.y;
    const int b  = bh >> 3, h = bh & 7;
    const int n0 = blockIdx.x * 64;

    const float* Q  = g_qkT + (size_t)bh * (kN * kD);
    const float* Kp = g_qkT + (size_t)kSeg + (size_t)bh * (kN * kD);

    const int af = t & 7, am = t >> 3;   // A loader
    const int kf = t & 7, kn = t >> 3;   // K loader

    if (t < 64) { runmax[t] = -1e30f; runsum[t] = 0.f; }
    __syncthreads();

    for (int mt = 0; mt < 4; mt++) {
        const int m0 = mt * 256;
        float acc[4][4][4];
#pragma unroll
        for (int g = 0; g < 4; g++)
#pragma unroll
            for (int i = 0; i < 4; i++)
#pragma unroll
                for (int j = 0; j < 4; j++) acc[g][i][j] = 0.f;

        // preload chunk 0
#pragma unroll
        for (int i = 0; i < 8; i++) {
            int m = am + i * 32;
            cp16(&As[m * 36 + af * 4], &Q[(size_t)(m0 + m) * kD + af * 4]);
        }
#pragma unroll
        for (int i = 0; i < 2; i++) {
            int n = kn + i * 32;
            cp16(&Ks[n * 36 + kf * 4], &Kp[(size_t)(n0 + n) * kD + kf * 4]);
        }
        cp_commit();

        for (int c = 0; c < 8; c++) {
            const int buf = c & 1;
            if (c < 7) {
                const int qc = (c + 1) * 32;
                const int nb = buf ^ 1;
#pragma unroll
                for (int i = 0; i < 8; i++) {
                    int m = am + i * 32;
                    cp16(&As[nb * 256 * 36 + m * 36 + af * 4],
                         &Q[(size_t)(m0 + m) * kD + qc + af * 4]);
                }
#pragma unroll
                for (int i = 0; i < 2; i++) {
                    int n = kn + i * 32;
                    cp16(&Ks[nb * 64 * 36 + n * 36 + kf * 4],
                         &Kp[(size_t)(n0 + n) * kD + qc + kf * 4]);
                }
                cp_commit();
                cp_wait<1>();
            } else {
                cp_wait<0>();
            }
            __syncthreads();

            const float* A_ = &As[buf * 256 * 36];
            const float* K_ = &Ks[buf * 64 * 36];
#pragma unroll
            for (int kg = 0; kg < 32; kg += 4) {
                float4 bv[4];
#pragma unroll
                for (int j = 0; j < 4; j++)
                    bv[j] = *(const float4*)&K_[(tx + 16 * j) * 36 + kg];
#pragma unroll
                for (int g = 0; g < 4; g++)
#pragma unroll
                    for (int i = 0; i < 4; i++) {
                        float4 av = *(const float4*)
                            &A_[(g * 64 + ty * 4 + i) * 36 + kg];
#pragma unroll
                        for (int j = 0; j < 4; j++) {
                            acc[g][i][j] = fmaf(av.x, bv[j].x, acc[g][i][j]);
                            acc[g][i][j] = fmaf(av.y, bv[j].y, acc[g][i][j]);
                            acc[g][i][j] = fmaf(av.z, bv[j].z, acc[g][i][j]);
                            acc[g][i][j] = fmaf(av.w, bv[j].w, acc[g][i][j]);
                        }
                    }
            }
            __syncthreads();
        }

        // scale by d^-0.5 = 1/16
#pragma unroll
        for (int g = 0; g < 4; g++)
#pragma unroll
            for (int i = 0; i < 4; i++)
#pragma unroll
                for (int j = 0; j < 4; j++) acc[g][i][j] *= 0.0625f;

        // column max over this 256-row tile
#pragma unroll
        for (int j = 0; j < 4; j++) {
            float tm = acc[0][0][j];
#pragma unroll
            for (int g = 0; g < 4; g++)
#pragma unroll
                for (int i = 0; i < 4; i++) tm = fmaxf(tm, acc[g][i][j]);
            red[ty * 64 + tx + 16 * j] = tm;
        }
        __syncthreads();
        if (t < 64) {
            float m_ = red[t];
#pragma unroll
            for (int r = 1; r < 16; r++) m_ = fmaxf(m_, red[r * 64 + t]);
            float nn = fmaxf(runmax[t], m_);
            runsum[t] *= __expf(runmax[t] - nn);
            runmax[t] = nn;
            nmv[t] = nn;
        }
        __syncthreads();

        // column sum of exp(S - newmax), plus diagonal capture
#pragma unroll
        for (int j = 0; j < 4; j++) {
            float nn = nmv[tx + 16 * j];
            float s = 0.f;
#pragma unroll
            for (int g = 0; g < 4; g++)
#pragma unroll
                for (int i = 0; i < 4; i++) s += __expf(acc[g][i][j] - nn);
            red[ty * 64 + tx + 16 * j] = s;
        }
#pragma unroll
        for (int g = 0; g < 4; g++)
#pragma unroll
            for (int i = 0; i < 4; i++) {
                int gm = m0 + g * 64 + ty * 4 + i;
#pragma unroll
                for (int j = 0; j < 4; j++) {
                    int gn = n0 + tx + 16 * j;
                    if (gm == gn) diagS[tx + 16 * j] = acc[g][i][j];
                }
            }
        __syncthreads();
        if (t < 64) {
            float s = 0.f;
#pragma unroll
            for (int r = 0; r < 16; r++) s += red[r * 64 + t];
            runsum[t] += s;
        }
        __syncthreads();
    }

    if (t < 64) {
        float da = __expf(diagS[t] - runmax[t]) / runsum[t];
        g_diag[((size_t)b * kN + (n0 + t)) * kH + h] = da;
    }
}

// ---------------------------------------------------------------------------
// Kernel 3: out = (diag .* v) @ W0 + b0    [4096,2048] @ [2048,256]
// (unchanged from round 1 — ~10% of runtime)
// ---------------------------------------------------------------------------
__global__ __launch_bounds__(256, 4)
void out_gemm_kernel(const float* __restrict__ W0,
                     const float* __restrict__ b0,
                     float* __restrict__ out)
{
    __shared__ float As[64][33];
    __shared__ float Ws[32][64];
    __shared__ float dsm[64][8];

    const int t  = threadIdx.x;
    const int tx = t & 15, ty = t >> 4;
    const int c0 = blockIdx.x * 64;
    const int r0 = blockIdx.y * 64;
    const float* vseg = g_qkv + 2ull * kSeg;

    for (int idx = t; idx < 512; idx += 256)
        dsm[idx >> 3][idx & 7] = g_diag[(size_t)(r0 + (idx >> 3)) * kH + (idx & 7)];
    __syncthreads();

    float acc[4][4];
#pragma unroll
    for (int i = 0; i < 4; i++)
#pragma unroll
        for (int j = 0; j < 4; j++) acc[i][j] = 0.f;

    const int kkA = t & 31, mbA = t >> 5;
    const int cW  = t & 63, kbW = t >> 6;

    for (int k0 = 0; k0 < kDH; k0 += 32) {
#pragma unroll
        for (int i = 0; i < 8; i++) {
            int m = mbA + i * 8;
            As[m][kkA] = dsm[m][kkA & 7] *
                         vseg[(size_t)(r0 + m) * kDH + k0 + kkA];
        }
#pragma unroll
        for (int i = 0; i < 8; i++) {
            int k2 = kbW + i * 4;
            Ws[k2][cW] = W0[(size_t)(k0 + k2) * kD + c0 + cW];
        }
        __syncthreads();
#pragma unroll
        for (int kq = 0; kq < 32; kq++) {
            float a[4];
#pragma unroll
            for (int i = 0; i < 4; i++) a[i] = As[ty * 4 + i][kq];
            float4 bv = *(const float4*)&Ws[kq][tx * 4];
            float b[4] = {bv.x, bv.y, bv.z, bv.w};
#pragma unroll
            for (int i = 0; i < 4; i++)
#pragma unroll
                for (int j = 0; j < 4; j++)
                    acc[i][j] = fmaf(a[i], b[j], acc[i][j]);
        }
        __syncthreads();
    }

#pragma unroll
    for (int i = 0; i < 4; i++) {
        int r = r0 + ty * 4 + i;
        int c = c0 + tx * 4;
        float4 v;
        v.x = acc[i][0] + b0[c + 0];
        v.y = acc[i][1] + b0[c + 1];
        v.z = acc[i][2] + b0[c + 2];
        v.w = acc[i][3] + b0[c + 3];
        *(float4*)&out[(size_t)r * kD + c] = v;
    }
}

// ---------------------------------------------------------------------------
extern "C" void kernel_launch(void* const* d_in, const int* in_sizes, int n_in,
                              void* d_out, int out_size)
{
    const float *x = nullptr, *Wqkv = nullptr, *bqkv = nullptr,
                *W0 = nullptr, *b0 = nullptr;
    for (int i = 0; i < n_in; i++) {
        switch (in_sizes[i]) {
            case kRows * kD: x    = (const float*)d_in[i]; break;
            case kD * kC3:   Wqkv = (const float*)d_in[i]; break;
            case kC3:        bqkv = (const float*)d_in[i]; break;
            case kDH * kD:   W0   = (const float*)d_in[i]; break;
            case kD:         b0   = (const float*)d_in[i]; break;
            default: break;
        }
    }
    float* out = (float*)d_out;

    const size_t smem1 = (size_t)(2 * 128 * 36 + 2 * 32 * 132) * sizeof(float);
    const size_t smem2 = (size_t)(2 * 256 * 36 + 2 * 64 * 36 + 16 * 64 + 4 * 64)
                       * sizeof(float);
    static bool attr_done = false;
    if (!attr_done) {
        cudaFuncSetAttribute(qkv_gemm_kernel,
                             cudaFuncAttributeMaxDynamicSharedMemorySize, (int)smem1);
        cudaFuncSetAttribute(score_diag_kernel,
                             cudaFuncAttributeMaxDynamicSharedMemorySize, (int)smem2);
        attr_done = true;
    }

    qkv_gemm_kernel<<<dim3(kC3 / 128, kRows / 128), 256, smem1>>>(x, Wqkv, bqkv);
    transpose_qk_kernel<<<2048, 256>>>();
    score_diag_kernel<<<dim3(kN / 64, kB * kH), 256, smem2>>>();
    out_gemm_kernel<<<dim3(kD / 64, kRows / 64), 256>>>(W0, b0, out);
}

// round 7
// speedup vs baseline: 1.2398x; 1.0429x over previous
#include <cuda_runtime.h>
#include <cstdint>

// Problem constants
constexpr int kB = 4;
constexpr int kN = 1024;
constexpr int kD = 256;
constexpr int kH = 8;
constexpr int kDH  = kD * kH;          // 2048
constexpr int kNDH = kN * kDH;         // 2097152
constexpr int kSeg = kB * kNDH;        // 8388608  (q/k/v segment, floats)
constexpr int kC3  = 3 * kDH;          // 6144
constexpr int kRows = kB * kN;         // 4096

// Scratch (device globals; no dynamic allocation allowed)
__device__ float g_qkv[3ull * kSeg];   // ~100.7 MB : QKV in reference flat layout
__device__ float g_qkT[2ull * kSeg];   // ~64 MB    : q,k transposed [seg][b][h][n][qd]
__device__ float g_diag[kRows * kH];
__device__ float g_part2[2][kRows * kD];  // k3 K-split partials

// ---------------- cp.async helpers ----------------
__device__ __forceinline__ void cp16(void* smem_dst, const void* gmem_src) {
    unsigned s = (unsigned)__cvta_generic_to_shared(smem_dst);
    asm volatile("cp.async.cg.shared.global [%0], [%1], 16;\n" :: "r"(s), "l"(gmem_src));
}
__device__ __forceinline__ void cp_commit() {
    asm volatile("cp.async.commit_group;\n");
}
template <int N>
__device__ __forceinline__ void cp_wait() {
    asm volatile("cp.async.wait_group %0;\n" :: "n"(N));
}

// ---------------------------------------------------------------------------
// Kernel 1: QKV = x @ Wqkv + bqkv     [4096,256] @ [256,6144]
// (round-2 proven version, verbatim)
// ---------------------------------------------------------------------------
__global__ __launch_bounds__(256, 2)
void qkv_gemm_kernel(const float* __restrict__ x,
                     const float* __restrict__ W,
                     const float* __restrict__ bias)
{
    extern __shared__ float sm[];
    float* As = sm;                    // [2][128][36]
    float* Bs = sm + 2 * 128 * 36;     // [2][32][132]

    const int t  = threadIdx.x;
    const int tx = t & 15, ty = t >> 4;
    const int r0 = blockIdx.y * 128;
    const int c0 = blockIdx.x * 128;

    const int af = t & 7,  am = t >> 3;
    const int bc = t & 31, bk = t >> 5;

    float acc[8][8];
#pragma unroll
    for (int i = 0; i < 8; i++)
#pragma unroll
        for (int j = 0; j < 8; j++) acc[i][j] = 0.f;

#pragma unroll
    for (int i = 0; i < 4; i++) {
        int m = am + i * 32;
        cp16(&As[m * 36 + af * 4], &x[(size_t)(r0 + m) * kD + af * 4]);
    }
#pragma unroll
    for (int i = 0; i < 4; i++) {
        int k = bk + i * 8;
        cp16(&Bs[k * 132 + bc * 4], &W[(size_t)k * kC3 + c0 + bc * 4]);
    }
    cp_commit();

    for (int c = 0; c < 8; c++) {
        const int buf = c & 1;
        if (c < 7) {
            const int kc = (c + 1) * 32;
            const int nb = buf ^ 1;
#pragma unroll
            for (int i = 0; i < 4; i++) {
                int m = am + i * 32;
                cp16(&As[nb * 128 * 36 + m * 36 + af * 4],
                     &x[(size_t)(r0 + m) * kD + kc + af * 4]);
            }
#pragma unroll
            for (int i = 0; i < 4; i++) {
                int k = bk + i * 8;
                cp16(&Bs[nb * 32 * 132 + k * 132 + bc * 4],
                     &W[(size_t)(kc + k) * kC3 + c0 + bc * 4]);
            }
            cp_commit();
            cp_wait<1>();
        } else {
            cp_wait<0>();
        }
        __syncthreads();

        const float* A_ = &As[buf * 128 * 36];
        const float* B_ = &Bs[buf * 32 * 132];
#pragma unroll
        for (int kg = 0; kg < 32; kg += 4) {
            float4 av[8];
#pragma unroll
            for (int gi = 0; gi < 2; gi++)
#pragma unroll
                for (int i = 0; i < 4; i++)
                    av[gi * 4 + i] =
                        *(const float4*)&A_[(gi * 64 + ty * 4 + i) * 36 + kg];
#pragma unroll
            for (int kk = 0; kk < 4; kk++) {
                float4 b0 = *(const float4*)&B_[(kg + kk) * 132 + tx * 4];
                float4 b1 = *(const float4*)&B_[(kg + kk) * 132 + tx * 4 + 64];
#pragma unroll
                for (int r = 0; r < 8; r++) {
                    float a = (kk == 0) ? av[r].x : (kk == 1) ? av[r].y
                             : (kk == 2) ? av[r].z : av[r].w;
                    acc[r][0] = fmaf(a, b0.x, acc[r][0]);
                    acc[r][1] = fmaf(a, b0.y, acc[r][1]);
                    acc[r][2] = fmaf(a, b0.z, acc[r][2]);
                    acc[r][3] = fmaf(a, b0.w, acc[r][3]);
                    acc[r][4] = fmaf(a, b1.x, acc[r][4]);
                    acc[r][5] = fmaf(a, b1.y, acc[r][5]);
                    acc[r][6] = fmaf(a, b1.z, acc[r][6]);
                    acc[r][7] = fmaf(a, b1.w, acc[r][7]);
                }
            }
        }
        __syncthreads();
    }

#pragma unroll
    for (int gi = 0; gi < 2; gi++)
#pragma unroll
        for (int i = 0; i < 4; i++) {
            int r  = r0 + gi * 64 + ty * 4 + i;
            int rr = gi * 4 + i;
#pragma unroll
            for (int gj = 0; gj < 2; gj++) {
                int c = c0 + gj * 64 + tx * 4;
                float4 v;
                v.x = acc[rr][gj * 4 + 0] + bias[c + 0];
                v.y = acc[rr][gj * 4 + 1] + bias[c + 1];
                v.z = acc[rr][gj * 4 + 2] + bias[c + 2];
                v.w = acc[rr][gj * 4 + 3] + bias[c + 3];
                *(float4*)&g_qkv[(size_t)r * kC3 + c] = v;
            }
        }
}

// ---------------------------------------------------------------------------
// Transpose kernel: q,k segments of g_qkv -> g_qkT[seg][b][h][n][qd]
// (round-2 proven version, verbatim; no scaling here)
// ---------------------------------------------------------------------------
__global__ __launch_bounds__(256)
void transpose_qk_kernel()
{
    __shared__ float smt[8][32][33];   // [h][qd][n]
    const int bid = blockIdx.x;
    const int qb  = bid & 7;
    const int nb  = (bid >> 3) & 31;
    const int b   = (bid >> 8) & 3;
    const int seg = bid >> 10;
    const int t   = threadIdx.x;

    const float* src = g_qkv + (size_t)seg * kSeg + (size_t)b * kNDH
                     + (size_t)(nb * 32) * kDH + qb * 32 * 8;
    {
        const int nl = t >> 3, f = t & 7;
        const int h0 = (f & 1) * 4, q0 = f >> 1;
#pragma unroll
        for (int i = 0; i < 8; i++) {
            float4 v = *(const float4*)&src[(size_t)nl * kDH + (f + i * 8) * 4];
            int ql = q0 + i * 4;
            smt[h0 + 0][ql][nl] = v.x;
            smt[h0 + 1][ql][nl] = v.y;
            smt[h0 + 2][ql][nl] = v.z;
            smt[h0 + 3][ql][nl] = v.w;
        }
    }
    __syncthreads();
    {
        const int q4 = (t & 7) * 4, hn = t >> 3;
#pragma unroll
        for (int i = 0; i < 8; i++) {
            int idx = hn + i * 32;
            int h = idx >> 5, n = idx & 31;
            float4 v;
            v.x = smt[h][q4 + 0][n];
            v.y = smt[h][q4 + 1][n];
            v.z = smt[h][q4 + 2][n];
            v.w = smt[h][q4 + 3][n];
            float* dst = g_qkT + (size_t)seg * kSeg
                       + (((size_t)(b * 8 + h) * kN + nb * 32 + n) * kD)
                       + qb * 32 + q4;
            *(float4*)dst = v;
        }
    }
}

// ---------------------------------------------------------------------------
// Kernel 2: per (b,h): S[m,n] = (1/16) q_m . k_n ; softmax over m per column;
// keep only diagonal attn. CTA: 128 n-cols, m swept in 8 tiles of 128.
// Inner loop = k1's proven conflict-free structure:
//   A (Q rows) m-major [128][36] via cp.async dbl-buffer,
//   B (K cols) k-major [32][132] via reg-prefetched LDG + STS dbl-buffer.
// 256 threads, 8x8 microtile. grid(8 ntiles, 32 bh).
// ---------------------------------------------------------------------------
__global__ __launch_bounds__(256, 2)
void score_diag_kernel()
{
    extern __shared__ float sm[];
    float* As     = sm;                       // [2][128*36]
    float* Ks     = sm + 2 * 4608;            // [2][32*132]
    float* red    = sm + 2 * 4608 + 2 * 4224; // [16*128]
    float* runmax = red + 2048;               // [128]
    float* runsum = runmax + 128;             // [128]
    float* nmv    = runsum + 128;             // [128]
    float* diagS  = nmv + 128;                // [128]

    const int t  = threadIdx.x;
    const int tx = t & 15, ty = t >> 4;
    const int bh = blockIdx.y;
    const int b  = bh >> 3, h = bh & 7;
    const int n0 = blockIdx.x * 128;

    const float* Q  = g_qkT + (size_t)bh * (kN * kD);
    const float* Kp = g_qkT + (size_t)kSeg + (size_t)bh * (kN * kD);

    const int af = t & 7, am = t >> 3;   // A loader
    const int kq = t & 7, nl = t >> 3;   // K loader: f4 k-col kq, n rows nl+32i

    if (t < 128) { runmax[t] = -1e30f; runsum[t] = 0.f; }
    __syncthreads();

    for (int mt = 0; mt < 8; mt++) {
        const int m0 = mt * 128;
        float acc[8][8];
#pragma unroll
        for (int i = 0; i < 8; i++)
#pragma unroll
            for (int j = 0; j < 8; j++) acc[i][j] = 0.f;

        // preload chunk 0: A via cp.async, K into regs
        float4 kreg[4];
#pragma unroll
        for (int i = 0; i < 4; i++) {
            int m = am + i * 32;
            cp16(&As[m * 36 + af * 4], &Q[(size_t)(m0 + m) * kD + af * 4]);
        }
#pragma unroll
        for (int i = 0; i < 4; i++)
            kreg[i] = *(const float4*)&Kp[(size_t)(n0 + nl + 32 * i) * kD + kq * 4];
        cp_commit();

        for (int c = 0; c < 8; c++) {
            const int buf = c & 1;
            // store K chunk c (k-major) into Ks[buf]
            {
                float* kb_ = &Ks[buf * 4224];
#pragma unroll
                for (int i = 0; i < 4; i++) {
                    int n = nl + 32 * i;
                    kb_[(kq * 4 + 0) * 132 + n] = kreg[i].x;
                    kb_[(kq * 4 + 1) * 132 + n] = kreg[i].y;
                    kb_[(kq * 4 + 2) * 132 + n] = kreg[i].z;
                    kb_[(kq * 4 + 3) * 132 + n] = kreg[i].w;
                }
            }
            if (c < 7) {
                const int kc = (c + 1) * 32;
#pragma unroll
                for (int i = 0; i < 4; i++) {
                    int m = am + i * 32;
                    cp16(&As[(buf ^ 1) * 4608 + m * 36 + af * 4],
                         &Q[(size_t)(m0 + m) * kD + kc + af * 4]);
                }
                cp_commit();
#pragma unroll
                for (int i = 0; i < 4; i++)
                    kreg[i] = *(const float4*)
                        &Kp[(size_t)(n0 + nl + 32 * i) * kD + kc + kq * 4];
                cp_wait<1>();
            } else {
                cp_wait<0>();
            }
            __syncthreads();

            const float* A_ = &As[buf * 4608];
            const float* K_ = &Ks[buf * 4224];
#pragma unroll
            for (int kg = 0; kg < 32; kg += 4) {
                float4 av[8];
#pragma unroll
                for (int gi = 0; gi < 2; gi++)
#pragma unroll
                    for (int i = 0; i < 4; i++)
                        av[gi * 4 + i] =
                            *(const float4*)&A_[(gi * 64 + ty * 4 + i) * 36 + kg];
#pragma unroll
                for (int kk = 0; kk < 4; kk++) {
                    float4 b0v = *(const float4*)&K_[(kg + kk) * 132 + tx * 4];
                    float4 b1v = *(const float4*)&K_[(kg + kk) * 132 + tx * 4 + 64];
#pragma unroll
                    for (int r = 0; r < 8; r++) {
                        float a = (kk == 0) ? av[r].x : (kk == 1) ? av[r].y
                                 : (kk == 2) ? av[r].z : av[r].w;
                        acc[r][0] = fmaf(a, b0v.x, acc[r][0]);
                        acc[r][1] = fmaf(a, b0v.y, acc[r][1]);
                        acc[r][2] = fmaf(a, b0v.z, acc[r][2]);
                        acc[r][3] = fmaf(a, b0v.w, acc[r][3]);
                        acc[r][4] = fmaf(a, b1v.x, acc[r][4]);
                        acc[r][5] = fmaf(a, b1v.y, acc[r][5]);
                        acc[r][6] = fmaf(a, b1v.z, acc[r][6]);
                        acc[r][7] = fmaf(a, b1v.w, acc[r][7]);
                    }
                }
            }
            __syncthreads();
        }

        // ---- epilogue: scale + online column softmax over this 128-row tile
#pragma unroll
        for (int r = 0; r < 8; r++)
#pragma unroll
            for (int j = 0; j < 8; j++) acc[r][j] *= 0.0625f;

        // per-thread column max over its 8 rows
#pragma unroll
        for (int jj = 0; jj < 8; jj++) {
            int cl = (jj >> 2) * 64 + tx * 4 + (jj & 3);
            float tm = acc[0][jj];
#pragma unroll
            for (int r = 1; r < 8; r++) tm = fmaxf(tm, acc[r][jj]);
            red[ty * 128 + cl] = tm;
        }
        __syncthreads();
        if (t < 128) {
            float m_ = red[t];
#pragma unroll
            for (int r = 1; r < 16; r++) m_ = fmaxf(m_, red[r * 128 + t]);
            float nn = fmaxf(runmax[t], m_);
            runsum[t] *= __expf(runmax[t] - nn);
            runmax[t] = nn;
            nmv[t] = nn;
        }
        __syncthreads();

        // per-thread exp-sum + diagonal capture
#pragma unroll
        for (int jj = 0; jj < 8; jj++) {
            int cl = (jj >> 2) * 64 + tx * 4 + (jj & 3);
            float nn = nmv[cl];
            float s = 0.f;
#pragma unroll
            for (int r = 0; r < 8; r++) {
                s += __expf(acc[r][jj] - nn);
                int rl = (r >> 2) * 64 + ty * 4 + (r & 3);
                if (m0 + rl == n0 + cl) diagS[cl] = acc[r][jj];
            }
            red[ty * 128 + cl] = s;
        }
        __syncthreads();
        if (t < 128) {
            float s = red[t];
#pragma unroll
            for (int r = 1; r < 16; r++) s += red[r * 128 + t];
            runsum[t] += s;
        }
        __syncthreads();
    }

    if (t < 128) {
        float da = __expf(diagS[t] - runmax[t]) / runsum[t];
        g_diag[((size_t)b * kN + (n0 + t)) * kH + h] = da;
    }
}

// ---------------------------------------------------------------------------
// Kernel 3: partial = (diag .* v) @ W0, K-split 2.  [4096,2048]@[2048,256]
// CTA 128m x 64n over a 1024-wide K half. W0 staged k-major via direct
// cp.async (it is [K][N] row-major). A staged with fused diag multiply.
// 256 threads, 8x4 microtile. grid(4 ctiles, 32 mtiles, 2 ksplit).
// ---------------------------------------------------------------------------
__global__ __launch_bounds__(256, 2)
void out_gemm_kernel(const float* __restrict__ W0)
{
    extern __shared__ float sm[];
    float* As  = sm;                    // [2][128*36]
    float* Ws  = sm + 2 * 4608;         // [2][32*68]
    float* dsm = sm + 2 * 4608 + 2 * 2176;  // [128*8]

    const int t  = threadIdx.x;
    const int tx = t & 15, ty = t >> 4;
    const int c0 = blockIdx.x * 64;
    const int r0 = blockIdx.y * 128;
    const int kb = blockIdx.z * 1024;
    const float* vseg = g_qkv + 2ull * kSeg;
    float* dst = g_part2[blockIdx.z];

    for (int idx = t; idx < 1024; idx += 256)
        dsm[idx] = g_diag[(size_t)(r0 + (idx >> 3)) * kH + (idx & 7)];

    const int af = t & 7,  am = t >> 3;   // A loader: f4 col af, rows am+32i
    const int wc = t & 15, wk = t >> 4;   // W loader: f4 col wc, k rows wk+16i

    float acc[8][4];
#pragma unroll
    for (int i = 0; i < 8; i++)
#pragma unroll
        for (int j = 0; j < 4; j++) acc[i][j] = 0.f;

    // preload chunk 0
    float4 areg[4];
#pragma unroll
    for (int i = 0; i < 2; i++) {
        int k = wk + 16 * i;
        cp16(&Ws[k * 68 + wc * 4], &W0[(size_t)(kb + k) * kD + c0 + wc * 4]);
    }
    cp_commit();
#pragma unroll
    for (int i = 0; i < 4; i++) {
        int m = am + 32 * i;
        areg[i] = *(const float4*)&vseg[(size_t)(r0 + m) * kDH + kb + af * 4];
    }
    __syncthreads();   // dsm ready

    for (int c = 0; c < 32; c++) {
        const int buf = c & 1;
        // store A chunk c with fused diag multiply
        {
            const int hoff = (af * 4) & 4;
#pragma unroll
            for (int i = 0; i < 4; i++) {
                int m = am + 32 * i;
                float4 dv = *(const float4*)&dsm[m * 8 + hoff];
                float4 v = areg[i];
                v.x *= dv.x; v.y *= dv.y; v.z *= dv.z; v.w *= dv.w;
                *(float4*)&As[buf * 4608 + m * 36 + af * 4] = v;
            }
        }
        if (c < 31) {
            const int kc = (c + 1) * 32;
#pragma unroll
            for (int i = 0; i < 2; i++) {
                int k = wk + 16 * i;
                cp16(&Ws[(buf ^ 1) * 2176 + k * 68 + wc * 4],
                     &W0[(size_t)(kb + kc + k) * kD + c0 + wc * 4]);
            }
            cp_commit();
#pragma unroll
            for (int i = 0; i < 4; i++) {
                int m = am + 32 * i;
                areg[i] = *(const float4*)
                    &vseg[(size_t)(r0 + m) * kDH + kb + kc + af * 4];
            }
            cp_wait<1>();
        } else {
            cp_wait<0>();
        }
        __syncthreads();

        const float* A_ = &As[buf * 4608];
        const float* W_ = &Ws[buf * 2176];
#pragma unroll
        for (int kg = 0; kg < 32; kg += 4) {
            float4 av[8];
#pragma unroll
            for (int gi = 0; gi < 2; gi++)
#pragma unroll
                for (int i = 0; i < 4; i++)
                    av[gi * 4 + i] =
                        *(const float4*)&A_[(gi * 64 + ty * 4 + i) * 36 + kg];
#pragma unroll
            for (int kk = 0; kk < 4; kk++) {
                float4 bv = *(const float4*)&W_[(kg + kk) * 68 + tx * 4];
#pragma unroll
                for (int r = 0; r < 8; r++) {
                    float a = (kk == 0) ? av[r].x : (kk == 1) ? av[r].y
                             : (kk == 2) ? av[r].z : av[r].w;
                    acc[r][0] = fmaf(a, bv.x, acc[r][0]);
                    acc[r][1] = fmaf(a, bv.y, acc[r][1]);
                    acc[r][2] = fmaf(a, bv.z, acc[r][2]);
                    acc[r][3] = fmaf(a, bv.w, acc[r][3]);
                }
            }
        }
        __syncthreads();
    }

#pragma unroll
    for (int gi = 0; gi < 2; gi++)
#pragma unroll
        for (int i = 0; i < 4; i++) {
            int r = r0 + gi * 64 + ty * 4 + i;
            float4 v;
            v.x = acc[gi * 4 + i][0];
            v.y = acc[gi * 4 + i][1];
            v.z = acc[gi * 4 + i][2];
            v.w = acc[gi * 4 + i][3];
            *(float4*)&dst[(size_t)r * kD + c0 + tx * 4] = v;
        }
}

// ---------------------------------------------------------------------------
// Kernel 3b: out = part0 + part1 + b0
// ---------------------------------------------------------------------------
__global__ __launch_bounds__(256)
void out_combine(const float* __restrict__ b0, float* __restrict__ out)
{
    int i4 = blockIdx.x * 256 + threadIdx.x;     // float4 index, 262144 total
    float4 a = *(const float4*)&g_part2[0][(size_t)i4 * 4];
    float4 b = *(const float4*)&g_part2[1][(size_t)i4 * 4];
    float4 bb = *(const float4*)&b0[(i4 & 63) * 4];
    float4 v;
    v.x = a.x + b.x + bb.x;
    v.y = a.y + b.y + bb.y;
    v.z = a.z + b.z + bb.z;
    v.w = a.w + b.w + bb.w;
    *(float4*)&out[(size_t)i4 * 4] = v;
}

// ---------------------------------------------------------------------------
extern "C" void kernel_launch(void* const* d_in, const int* in_sizes, int n_in,
                              void* d_out, int out_size)
{
    const float *x = nullptr, *Wqkv = nullptr, *bqkv = nullptr,
                *W0 = nullptr, *b0 = nullptr;
    for (int i = 0; i < n_in; i++) {
        switch (in_sizes[i]) {
            case kRows * kD: x    = (const float*)d_in[i]; break;
            case kD * kC3:   Wqkv = (const float*)d_in[i]; break;
            case kC3:        bqkv = (const float*)d_in[i]; break;
            case kDH * kD:   W0   = (const float*)d_in[i]; break;
            case kD:         b0   = (const float*)d_in[i]; break;
            default: break;
        }
    }
    float* out = (float*)d_out;

    const size_t smem1 = (size_t)(2 * 128 * 36 + 2 * 32 * 132) * sizeof(float); // 70656
    const size_t smem2 = (size_t)(2 * 4608 + 2 * 4224 + 2048 + 512) * sizeof(float); // 80896
    const size_t smem3 = (size_t)(2 * 4608 + 2 * 2176 + 1024) * sizeof(float);  // 58368
    static bool attr_done = false;
    if (!attr_done) {
        cudaFuncSetAttribute(qkv_gemm_kernel,
                             cudaFuncAttributeMaxDynamicSharedMemorySize, (int)smem1);
        cudaFuncSetAttribute(score_diag_kernel,
                             cudaFuncAttributeMaxDynamicSharedMemorySize, (int)smem2);
        cudaFuncSetAttribute(out_gemm_kernel,
                             cudaFuncAttributeMaxDynamicSharedMemorySize, (int)smem3);
        attr_done = true;
    }

    qkv_gemm_kernel<<<dim3(kC3 / 128, kRows / 128), 256, smem1>>>(x, Wqkv, bqkv);
    transpose_qk_kernel<<<2048, 256>>>();
    score_diag_kernel<<<dim3(kN / 128, kB * kH), 256, smem2>>>();
    out_gemm_kernel<<<dim3(kD / 64, kRows / 128, 2), 256, smem3>>>(W0);
    out_combine<<<1024, 256>>>(b0, out);
}